// round 10
// baseline (speedup 1.0000x reference)
#include <cuda_runtime.h>
#include <cuda_bf16.h>
#include <math.h>
#include <stdint.h>

// Problem constants (fixed shapes per reference)
#define NN 4096
#define EE 256
#define KK 128
#define BB 64
#define DD 8

// ---------------- scratch (no allocations allowed) ----------------
__device__ float g_t0[NN * EE];
__device__ float g_hres[NN * EE];
__device__ float g_c[NN * KK];
__device__ float g_s[NN * KK];
__device__ float g_sfr[BB * KK * EE];
__device__ float g_sfi[BB * KK * EE];
__device__ float g_kf[KK * EE];
__device__ int   g_off[BB + 1];
// Activations, SLAB layout: 8 slabs [c][4096 rows][64 bf16 = 128B], SW128-swizzled.
// slabs 0-3 = hi cols 0..255, slabs 4-7 = lo cols 0..255.
__device__ __align__(128) __nv_bfloat16 g_x2a[NN * 512];
__device__ __align__(128) __nv_bfloat16 g_x2b[NN * 512];
// Weights, SLAB layout: 9 gemms x [nblk 4][c 8][64 rows][64 bf16], swizzled.
// c 0-3 = Whi, c 4-7 = Wlo.
__device__ __align__(128) __nv_bfloat16 g_wc[9 * 256 * 512];

// ---------------- helpers ----------------
__device__ __forceinline__ float silu(float v) {
    return v / (1.0f + __expf(-v));
}

__device__ __forceinline__ uint32_t smem_u32(const void* p) {
    uint32_t a;
    asm("{ .reg .u64 t; cvta.to.shared.u64 t, %1; cvt.u32.u64 %0, t; }" : "=r"(a) : "l"(p));
    return a;
}

#define SWZ(o) ((o) ^ (((o) >> 3) & 0x70))

#define LDMATRIX_X4(r0, r1, r2, r3, addr) \
    asm volatile("ldmatrix.sync.aligned.m8n8.x4.shared.b16 {%0,%1,%2,%3}, [%4];" \
                 : "=r"(r0), "=r"(r1), "=r"(r2), "=r"(r3) : "r"(addr))

#define MMA_BF16(c, a, b0, b1) \
    asm volatile("mma.sync.aligned.m16n8k16.row.col.f32.bf16.bf16.f32 " \
                 "{%0,%1,%2,%3},{%4,%5,%6,%7},{%8,%9},{%0,%1,%2,%3};" \
                 : "+f"((c)[0]), "+f"((c)[1]), "+f"((c)[2]), "+f"((c)[3]) \
                 : "r"((a)[0]), "r"((a)[1]), "r"((a)[2]), "r"((a)[3]), \
                   "r"(b0), "r"(b1))

#define MBAR_INIT(a, c) \
    asm volatile("mbarrier.init.shared.b64 [%0], %1;" :: "r"(a), "r"((uint32_t)(c)) : "memory")

#define MBAR_EXPECT_TX(a, n) \
    asm volatile("mbarrier.arrive.expect_tx.shared.b64 _, [%0], %1;" \
                 :: "r"(a), "r"((uint32_t)(n)) : "memory")

#define MBAR_WAIT(addr, ph) do { \
    uint32_t _m = (addr), _p = (uint32_t)(ph), _d; \
    asm volatile("{\n\t.reg .pred p;\n\tmbarrier.try_wait.parity.acquire.cta.shared::cta.b64 p, [%1], %2;\n\tselp.b32 %0, 1, 0, p;\n\t}" \
        : "=r"(_d) : "r"(_m), "r"(_p) : "memory"); \
    if (!_d) { \
        asm volatile("{\n\t.reg .pred P1;\n\tWL_%=:\n\tmbarrier.try_wait.parity.acquire.cta.shared::cta.b64 P1, [%0], %1, 0x989680;\n\t@P1 bra.uni WD_%=;\n\tbra.uni WL_%=;\n\tWD_%=:\n\t}" \
            :: "r"(_m), "r"(_p) : "memory"); \
    } \
} while (0)

#define CP_BULK(dst, src, bytes, mbar) \
    asm volatile("cp.async.bulk.shared::cta.global.mbarrier::complete_tx::bytes " \
                 "[%0], [%1], %2, [%3];" \
                 :: "r"(dst), "l"(src), "r"((uint32_t)(bytes)), "r"(mbar) : "memory")

// ============================================================================
// HMMA GEMM, FULLY RESIDENT: out = silu(A @ W^T) [+ skip]
// A2: slabbed (8 x [4096][128B], swizzled).  Wc: slabbed per-nblk 64KB.
// 3-term split: Ahi*Whi + Ahi*Wlo + Alo*Whi.
// CTA tile 128x64, 512 threads = 16 warps (4m x 4n), warp tile 32x16.
// Entire A slice (128KB) + W slice (64KB) resident in smem: 9 bulk copies
// issued upfront (one mbarrier per A chunk) -> mainloop has ZERO
// __syncthreads and no stage recycling; waits pass as data lands.
// ============================================================================
#define ASLAB (4096 * 128)            // bytes per activation slab (512KB)
#define A_CH  16384                    // per-chunk A bytes (128 rows x 128B)
#define W_PB  65536                    // W persistent bytes (8 slabs x 8KB)
#define GEMM_SMEM (W_PB + 8 * A_CH)    // 196608 -> 1 CTA/SM

__global__ void __launch_bounds__(512, 1) gemm_mma_kernel(
    const __nv_bfloat16* __restrict__ A2,
    const __nv_bfloat16* __restrict__ Wc,   // already offset to this gemm
    const float* __restrict__ skip,
    float* __restrict__ outf,
    __nv_bfloat16* __restrict__ out2)
{
    extern __shared__ char smem[];
    uint32_t sb = smem_u32(smem);            // [0,65536): W; then 8 A chunks
    __shared__ __align__(8) uint64_t mbars[9];  // 0-7: A chunks, 8: W

    int tid = threadIdx.x, wid = tid >> 5, lane = tid & 31;
    int m0 = blockIdx.y * 128, n0 = blockIdx.x * 64;
    int nb = blockIdx.x;
    int warp_m = (wid & 3) * 32, warp_n = (wid >> 2) * 16;

    uint32_t mbase = smem_u32(&mbars[0]);
    uint32_t wbar  = mbase + 8 * 8;

    if (tid == 0) {
#pragma unroll
        for (int i = 0; i < 9; i++) MBAR_INIT(mbase + i * 8, 1);
    }
    __syncthreads();

    const char* gA = (const char*)A2 + (size_t)m0 * 128;   // + c*ASLAB per chunk
    const char* gW = (const char*)Wc + (size_t)nb * W_PB;

    if (tid == 0) {
        MBAR_EXPECT_TX(wbar, W_PB);
        CP_BULK(sb, gW, W_PB, wbar);
#pragma unroll
        for (int c = 0; c < 8; c++) {
            MBAR_EXPECT_TX(mbase + c * 8, A_CH);
            CP_BULK(sb + W_PB + c * A_CH, gA + (size_t)c * ASLAB, A_CH, mbase + c * 8);
        }
    }

    float acc[2][2][4];
#pragma unroll
    for (int i = 0; i < 2; i++)
#pragma unroll
        for (int j = 0; j < 2; j++)
#pragma unroll
            for (int q = 0; q < 4; q++) acc[i][j][q] = 0.f;

    int arow0 = warp_m + (lane & 15);
    int brow  = warp_n + (lane & 15);
    int hi16  = (lane >> 4) * 16;

    MBAR_WAIT(wbar, 0);

#pragma unroll
    for (int ch = 0; ch < 8; ch++) {
        MBAR_WAIT(mbase + ch * 8, 0);

        uint32_t aB = sb + W_PB + ch * A_CH;
        const bool isHi = (ch < 4);
        const uint32_t whiB = sb + (uint32_t)((isHi ? ch : (ch - 4)) * 8192);
        const uint32_t wloB = sb + (uint32_t)((4 + ch) * 8192);

        // fragment double-buffering over kh (no block barriers anywhere)
        uint32_t a[2][2][4], bh[2][4], bl[2][4];
        {
            uint32_t o0 = SWZ((uint32_t)(arow0 * 128 + hi16));
            uint32_t o1 = SWZ((uint32_t)((arow0 + 16) * 128 + hi16));
            LDMATRIX_X4(a[0][0][0], a[0][0][1], a[0][0][2], a[0][0][3], aB + o0);
            LDMATRIX_X4(a[0][1][0], a[0][1][1], a[0][1][2], a[0][1][3], aB + o1);
            uint32_t bo = SWZ((uint32_t)(brow * 128 + hi16));
            LDMATRIX_X4(bh[0][0], bh[0][1], bh[0][2], bh[0][3], whiB + bo);
            if (isHi) LDMATRIX_X4(bl[0][0], bl[0][1], bl[0][2], bl[0][3], wloB + bo);
        }

#pragma unroll
        for (int kh = 0; kh < 4; kh++) {
            const int cur = kh & 1, nxt = cur ^ 1;
            if (kh < 3) {
                uint32_t ko = (uint32_t)((kh + 1) * 32 + hi16);
                uint32_t o0 = SWZ((uint32_t)(arow0 * 128) + ko);
                uint32_t o1 = SWZ((uint32_t)((arow0 + 16) * 128) + ko);
                LDMATRIX_X4(a[nxt][0][0], a[nxt][0][1], a[nxt][0][2], a[nxt][0][3], aB + o0);
                LDMATRIX_X4(a[nxt][1][0], a[nxt][1][1], a[nxt][1][2], a[nxt][1][3], aB + o1);
                uint32_t bo = SWZ((uint32_t)(brow * 128) + ko);
                LDMATRIX_X4(bh[nxt][0], bh[nxt][1], bh[nxt][2], bh[nxt][3], whiB + bo);
                if (isHi) LDMATRIX_X4(bl[nxt][0], bl[nxt][1], bl[nxt][2], bl[nxt][3], wloB + bo);
            }
#pragma unroll
            for (int mt = 0; mt < 2; mt++)
#pragma unroll
                for (int j = 0; j < 2; j++)
                    MMA_BF16(acc[mt][j], a[cur][mt], bh[cur][j], bh[cur][j + 2]);
            if (isHi) {
#pragma unroll
                for (int mt = 0; mt < 2; mt++)
#pragma unroll
                    for (int j = 0; j < 2; j++)
                        MMA_BF16(acc[mt][j], a[cur][mt], bl[cur][j], bl[cur][j + 2]);
            }
        }
    }

    // ---------------- epilogue ----------------
    char* o2 = (char*)out2;
    int r0 = lane >> 2, cp = (lane & 3) * 2;
#pragma unroll
    for (int mt = 0; mt < 2; mt++) {
#pragma unroll
        for (int j = 0; j < 2; j++) {
            int n = n0 + warp_n + j * 8 + cp;
#pragma unroll
            for (int half = 0; half < 2; half++) {
                int m = m0 + warp_m + mt * 16 + r0 + half * 8;
                float v0 = acc[mt][j][half * 2 + 0];
                float v1 = acc[mt][j][half * 2 + 1];
                v0 = silu(v0);
                v1 = silu(v1);
                if (skip) {
                    float2 sk = *reinterpret_cast<const float2*>(skip + (size_t)m * 256 + n);
                    v0 += sk.x; v1 += sk.y;
                }
                if (outf) {
                    float2 o; o.x = v0; o.y = v1;
                    *reinterpret_cast<float2*>(outf + (size_t)m * 256 + n) = o;
                }
                if (out2) {
                    __nv_bfloat16 h0 = __float2bfloat16(v0);
                    __nv_bfloat16 h1 = __float2bfloat16(v1);
                    __nv_bfloat162 hh; hh.x = h0; hh.y = h1;
                    __nv_bfloat162 ll;
                    ll.x = __float2bfloat16(v0 - __bfloat162float(h0));
                    ll.y = __float2bfloat16(v1 - __bfloat162float(h1));
                    uint32_t loc = SWZ((uint32_t)(m * 128 + (n & 63) * 2));
                    *reinterpret_cast<__nv_bfloat162*>(
                        o2 + (size_t)(n >> 6) * ASLAB + loc) = hh;
                    *reinterpret_cast<__nv_bfloat162*>(
                        o2 + (size_t)(4 + (n >> 6)) * ASLAB + loc) = ll;
                }
            }
        }
    }
}

// ---------------- hi/lo conversion of h (slabbed, swizzled) ----------------
__global__ void conv_h_kernel(const float* __restrict__ h) {
    int idx = blockIdx.x * 256 + threadIdx.x;
    int m = idx >> 8, e = idx & 255;
    float v = h[idx];
    __nv_bfloat16 hi = __float2bfloat16(v);
    __nv_bfloat16 lo = __float2bfloat16(v - __bfloat162float(hi));
    uint32_t loc = SWZ((uint32_t)(m * 128 + (e & 63) * 2));
    char* base = (char*)g_x2a;
    *reinterpret_cast<__nv_bfloat16*>(base + (size_t)(e >> 6) * ASLAB + loc) = hi;
    *reinterpret_cast<__nv_bfloat16*>(base + (size_t)(4 + (e >> 6)) * ASLAB + loc) = lo;
}

// ---------------- weight conversion (slabbed, swizzled) ----------------
__global__ void conv_w_kernel(const float* __restrict__ Wpre,
                              const float* __restrict__ W0,
                              const float* __restrict__ Wres) {
    int g = blockIdx.y;
    int i = blockIdx.x * 256 + threadIdx.x;  // 0..65535
    int n = i >> 8, k = i & 255;
    const float* src = (g < 2) ? (Wpre + (size_t)g * 65536)
                     : (g == 2) ? W0
                     : (Wres + (size_t)(g - 3) * 65536);
    float v = src[i];
    __nv_bfloat16 hi = __float2bfloat16(v);
    __nv_bfloat16 lo = __float2bfloat16(v - __bfloat162float(hi));
    uint32_t loc = SWZ((uint32_t)((n & 63) * 128 + (k & 63) * 2));
    char* base = (char*)g_wc + (size_t)g * 262144 + (size_t)(n >> 6) * W_PB;
    *reinterpret_cast<__nv_bfloat16*>(base + (size_t)(k >> 6) * 8192 + loc) = hi;
    *reinterpret_cast<__nv_bfloat16*>(base + (size_t)(4 + (k >> 6)) * 8192 + loc) = lo;
}

// ---------------- segment offsets from sorted batch_seg ----------------
__global__ void seg_offsets_kernel(const int* __restrict__ seg) {
    int n = blockIdx.x * blockDim.x + threadIdx.x;
    if (n >= NN) return;
    int s = seg[n];
    if (n == 0) {
        for (int b = 0; b <= s; b++) g_off[b] = 0;
    } else {
        int p = seg[n - 1];
        for (int b = p + 1; b <= s; b++) g_off[b] = n;
    }
    if (n == NN - 1) {
        for (int b = s + 1; b <= BB; b++) g_off[b] = NN;
    }
}

// ---------------- dot products + cos/sin ----------------
__global__ void dot_kernel(const float* __restrict__ x,
                           const float* __restrict__ kvec,
                           const int* __restrict__ seg,
                           float* __restrict__ dot_out) {
    int n = blockIdx.x;
    int kk = threadIdx.x;  // 128
    int b = seg[n];
    float x0 = x[n * 3 + 0], x1 = x[n * 3 + 1], x2 = x[n * 3 + 2];
    const float* kr = kvec + ((size_t)b * KK + kk) * 3;
    float d = kr[0] * x0 + kr[1] * x1 + kr[2] * x2;
    dot_out[n * KK + kk] = d;
    float cv, sv;
    sincosf(d, &sv, &cv);
    g_c[n * KK + kk] = cv;
    g_s[n * KK + kk] = sv;
}

// ---------------- low-rank k-filter ----------------
__global__ void kf_kernel(const float* __restrict__ Wup,
                          const float* __restrict__ Wdn) {
    int e = threadIdx.x;
    int k = blockIdx.x;
    float a = 0.f;
#pragma unroll
    for (int d = 0; d < DD; d++) a += Wup[e * DD + d] * Wdn[d * KK + k];
    g_kf[k * EE + e] = a;
}

// ---------------- structure factors (kfilter folded in) ----------------
__global__ void __launch_bounds__(256, 4) sf_kernel() {
    int b  = blockIdx.z;
    int k0 = blockIdx.y * 32;
    int e0 = blockIdx.x * 32;
    int t = threadIdx.x;
    int e4 = t & 7;
    int ky = t >> 3;
    __shared__ float csh[32][32], ssh[32][32], hsh[32][32];
    int st = g_off[b], en = g_off[b + 1];
    float aR[4] = {0.f, 0.f, 0.f, 0.f};
    float aI[4] = {0.f, 0.f, 0.f, 0.f};
    for (int n0 = st; n0 < en; n0 += 32) {
#pragma unroll
        for (int l = 0; l < 4; l++) {
            int idx = t + 256 * l;
            int r = idx >> 5, c = idx & 31;
            int n = n0 + r;
            bool v = (n < en);
            csh[r][c] = v ? g_c[n * KK + k0 + c] : 0.f;
            ssh[r][c] = v ? g_s[n * KK + k0 + c] : 0.f;
            hsh[r][c] = v ? g_hres[(size_t)n * EE + e0 + c] : 0.f;
        }
        __syncthreads();
#pragma unroll
        for (int nn = 0; nn < 32; nn++) {
            float4 hv = *reinterpret_cast<float4*>(&hsh[nn][e4 * 4]);
            float cv = csh[nn][ky];
            float sv = ssh[nn][ky];
            aR[0] += cv * hv.x; aR[1] += cv * hv.y; aR[2] += cv * hv.z; aR[3] += cv * hv.w;
            aI[0] += sv * hv.x; aI[1] += sv * hv.y; aI[2] += sv * hv.z; aI[3] += sv * hv.w;
        }
        __syncthreads();
    }
    float4 f = *reinterpret_cast<float4*>(&g_kf[(k0 + ky) * EE + e0 + e4 * 4]);
    size_t idx = ((size_t)b * KK + k0 + ky) * EE + e0 + e4 * 4;
    float4 oR, oI;
    oR.x = aR[0] * f.x; oR.y = aR[1] * f.y; oR.z = aR[2] * f.z; oR.w = aR[3] * f.w;
    oI.x = aI[0] * f.x; oI.y = aI[1] * f.y; oI.z = aI[2] * f.z; oI.w = aI[3] * f.w;
    *reinterpret_cast<float4*>(&g_sfr[idx]) = oR;
    *reinterpret_cast<float4*>(&g_sfi[idx]) = oI;
}

// ---------------- back-projection; writes hi/lo bf16 (slabbed) --------------
__global__ void __launch_bounds__(256, 4) hupd_kernel(const int* __restrict__ seg) {
    int n0 = blockIdx.y * 32;
    int e0 = blockIdx.x * 32;
    int t = threadIdx.x;
    int e4 = t & 7;
    int ny = t >> 3;
    int n = n0 + ny;
    int b = seg[n];
    __shared__ float csh[32][32], ssh[32][32];
    float acc[4] = {0.f, 0.f, 0.f, 0.f};
    for (int k0c = 0; k0c < KK; k0c += 32) {
#pragma unroll
        for (int l = 0; l < 4; l++) {
            int idx = t + 256 * l;
            int r = idx >> 5, c = idx & 31;
            csh[r][c] = g_c[(n0 + r) * KK + k0c + c];
            ssh[r][c] = g_s[(n0 + r) * KK + k0c + c];
        }
        __syncthreads();
        const float* baseR = g_sfr + ((size_t)b * KK + k0c) * EE + e0 + e4 * 4;
        const float* baseI = g_sfi + ((size_t)b * KK + k0c) * EE + e0 + e4 * 4;
#pragma unroll
        for (int kk = 0; kk < 32; kk++) {
            float cv = csh[ny][kk];
            float sv = ssh[ny][kk];
            float4 pr = *reinterpret_cast<const float4*>(baseR + (size_t)kk * EE);
            float4 pi = *reinterpret_cast<const float4*>(baseI + (size_t)kk * EE);
            acc[0] += cv * pr.x + sv * pi.x;
            acc[1] += cv * pr.y + sv * pi.y;
            acc[2] += cv * pr.z + sv * pi.z;
            acc[3] += cv * pr.w + sv * pi.w;
        }
        __syncthreads();
    }
    __nv_bfloat16 hi[4], lo[4];
#pragma unroll
    for (int q = 0; q < 4; q++) {
        float v = 0.01f * acc[q];
        hi[q] = __float2bfloat16(v);
        lo[q] = __float2bfloat16(v - __bfloat162float(hi[q]));
    }
    int e = e0 + e4 * 4;
    uint32_t loc = SWZ((uint32_t)(n * 128 + (e & 63) * 2));
    char* base = (char*)g_x2a;
    *reinterpret_cast<uint2*>(base + (size_t)(e >> 6) * ASLAB + loc) =
        *reinterpret_cast<uint2*>(hi);
    *reinterpret_cast<uint2*>(base + (size_t)(4 + (e >> 6)) * ASLAB + loc) =
        *reinterpret_cast<uint2*>(lo);
}

// ---------------- launch ----------------
extern "C" void kernel_launch(void* const* d_in, const int* in_sizes, int n_in,
                              void* d_out, int out_size) {
    const float *h = nullptr, *x = nullptr, *kv = nullptr;
    const float *Wpre = nullptr, *Wdn = nullptr, *Wup = nullptr;
    const float *W0 = nullptr, *Wres = nullptr;
    const int* seg = nullptr;

    for (int i = 0; i < n_in; i++) {
        switch (in_sizes[i]) {
            case NN * EE:           h    = (const float*)d_in[i]; break;
            case NN * 3:            x    = (const float*)d_in[i]; break;
            case BB * KK * 3:       kv   = (const float*)d_in[i]; break;
            case NN:                seg  = (const int*)d_in[i];   break;
            case 2 * EE * EE:       Wpre = (const float*)d_in[i]; break;
            case DD * KK:           Wdn  = (const float*)d_in[i]; break;
            case EE * DD:           Wup  = (const float*)d_in[i]; break;
            case EE * EE:           W0   = (const float*)d_in[i]; break;
            case 3 * 2 * EE * EE:   Wres = (const float*)d_in[i]; break;
            default: break;
        }
    }

    float* out = (float*)d_out;
    float* out_hu  = out;            // (NN, EE)
    float* out_dot = out + NN * EE;  // (NN, KK)

    float *t0, *hres;
    __nv_bfloat16 *x2a, *x2b, *wc;
    cudaGetSymbolAddress((void**)&t0,   g_t0);
    cudaGetSymbolAddress((void**)&hres, g_hres);
    cudaGetSymbolAddress((void**)&x2a,  g_x2a);
    cudaGetSymbolAddress((void**)&x2b,  g_x2b);
    cudaGetSymbolAddress((void**)&wc,   g_wc);

    cudaFuncSetAttribute(gemm_mma_kernel,
                         cudaFuncAttributeMaxDynamicSharedMemorySize, GEMM_SMEM);
    dim3 ggrid(EE / 64, NN / 128);  // (4, 32) = 128 CTAs, 1 wave

    // conversions
    conv_w_kernel<<<dim3(256, 9), 256>>>(Wpre, W0, Wres);
    conv_h_kernel<<<NN * EE / 256, 256>>>(h);

    // pre-residual: x2b = silu(h@W0'), hres = h + silu(x2b@W1')
    gemm_mma_kernel<<<ggrid, 512, GEMM_SMEM>>>(x2a, wc + 0 * 131072, nullptr, nullptr, x2b);
    gemm_mma_kernel<<<ggrid, 512, GEMM_SMEM>>>(x2b, wc + 1 * 131072, h, hres, nullptr);

    // Ewald geometry path
    seg_offsets_kernel<<<(NN + 255) / 256, 256>>>(seg);
    dot_kernel<<<NN, KK>>>(x, kv, seg, out_dot);
    kf_kernel<<<KK, EE>>>(Wup, Wdn);
    sf_kernel<<<dim3(EE / 32, KK / 32, BB), 256>>>();
    hupd_kernel<<<dim3(EE / 32, NN / 32), 256>>>(seg);  // -> g_x2a (slabbed hi/lo)

    // update MLP: t0 = silu(hu @ W0^T)
    gemm_mma_kernel<<<ggrid, 512, GEMM_SMEM>>>(x2a, wc + 2 * 131072, nullptr, t0, x2b);

    // 3 residual blocks
    for (int i = 0; i < 3; i++) {
        const __nv_bfloat16* wa = wc + (size_t)(3 + 2 * i) * 131072;
        const __nv_bfloat16* wb = wc + (size_t)(4 + 2 * i) * 131072;
        gemm_mma_kernel<<<ggrid, 512, GEMM_SMEM>>>(x2b, wa, nullptr, nullptr, x2a);
        float* dstf = (i == 2) ? out_hu : t0;
        __nv_bfloat16* dst2 = (i == 2) ? nullptr : x2b;
        gemm_mma_kernel<<<ggrid, 512, GEMM_SMEM>>>(x2a, wb, t0, dstf, dst2);
    }
}

// round 11
// speedup vs baseline: 1.0102x; 1.0102x over previous
#include <cuda_runtime.h>
#include <cuda_bf16.h>
#include <math.h>
#include <stdint.h>

// Problem constants (fixed shapes per reference)
#define NN 4096
#define EE 256
#define KK 128
#define BB 64
#define DD 8

// ---------------- scratch (no allocations allowed) ----------------
__device__ float g_t0[NN * EE];
__device__ float g_hres[NN * EE];
__device__ float g_c[NN * KK];
__device__ float g_s[NN * KK];
__device__ float g_sfr[BB * KK * EE];
__device__ float g_sfi[BB * KK * EE];
__device__ float g_kf[KK * EE];
__device__ int   g_off[BB + 1];
// Activations, SLAB layout: 8 slabs [c][4096 rows][64 bf16 = 128B], SW128-swizzled.
// slabs 0-3 = hi cols 0..255, slabs 4-7 = lo cols 0..255.
__device__ __align__(128) __nv_bfloat16 g_x2a[NN * 512];
__device__ __align__(128) __nv_bfloat16 g_x2b[NN * 512];
// Weights, SLAB layout: 9 gemms x [nblk 4][c 8][64 rows][64 bf16], swizzled.
// c 0-3 = Whi, c 4-7 = Wlo.
__device__ __align__(128) __nv_bfloat16 g_wc[9 * 256 * 512];

// ---------------- helpers ----------------
__device__ __forceinline__ float silu(float v) {
    return v / (1.0f + __expf(-v));
}

__device__ __forceinline__ uint32_t smem_u32(const void* p) {
    uint32_t a;
    asm("{ .reg .u64 t; cvta.to.shared.u64 t, %1; cvt.u32.u64 %0, t; }" : "=r"(a) : "l"(p));
    return a;
}

#define SWZ(o) ((o) ^ (((o) >> 3) & 0x70))

#define LDMATRIX_X4(r0, r1, r2, r3, addr) \
    asm volatile("ldmatrix.sync.aligned.m8n8.x4.shared.b16 {%0,%1,%2,%3}, [%4];" \
                 : "=r"(r0), "=r"(r1), "=r"(r2), "=r"(r3) : "r"(addr))

#define MMA_BF16(c, a, b0, b1) \
    asm volatile("mma.sync.aligned.m16n8k16.row.col.f32.bf16.bf16.f32 " \
                 "{%0,%1,%2,%3},{%4,%5,%6,%7},{%8,%9},{%0,%1,%2,%3};" \
                 : "+f"((c)[0]), "+f"((c)[1]), "+f"((c)[2]), "+f"((c)[3]) \
                 : "r"((a)[0]), "r"((a)[1]), "r"((a)[2]), "r"((a)[3]), \
                   "r"(b0), "r"(b1))

#define MBAR_INIT(a, c) \
    asm volatile("mbarrier.init.shared.b64 [%0], %1;" :: "r"(a), "r"((uint32_t)(c)) : "memory")

#define MBAR_EXPECT_TX(a, n) \
    asm volatile("mbarrier.arrive.expect_tx.shared.b64 _, [%0], %1;" \
                 :: "r"(a), "r"((uint32_t)(n)) : "memory")

#define MBAR_WAIT(addr, ph) do { \
    uint32_t _m = (addr), _p = (uint32_t)(ph), _d; \
    asm volatile("{\n\t.reg .pred p;\n\tmbarrier.try_wait.parity.acquire.cta.shared::cta.b64 p, [%1], %2;\n\tselp.b32 %0, 1, 0, p;\n\t}" \
        : "=r"(_d) : "r"(_m), "r"(_p) : "memory"); \
    if (!_d) { \
        asm volatile("{\n\t.reg .pred P1;\n\tWL_%=:\n\tmbarrier.try_wait.parity.acquire.cta.shared::cta.b64 P1, [%0], %1, 0x989680;\n\t@P1 bra.uni WD_%=;\n\tbra.uni WL_%=;\n\tWD_%=:\n\t}" \
            :: "r"(_m), "r"(_p) : "memory"); \
    } \
} while (0)

#define CP_BULK(dst, src, bytes, mbar) \
    asm volatile("cp.async.bulk.shared::cta.global.mbarrier::complete_tx::bytes " \
                 "[%0], [%1], %2, [%3];" \
                 :: "r"(dst), "l"(src), "r"((uint32_t)(bytes)), "r"(mbar) : "memory")

// packed fp32x2 FMA helpers (SASS FFMA2 — PTX-only pattern)
#define PACK2(dst, v) \
    asm("mov.b64 %0, {%1, %1};" : "=l"(dst) : "f"(v))
#define FMA2(acc, a, b) \
    asm("fma.rn.f32x2 %0, %1, %2, %0;" : "+l"(acc) : "l"(a), "l"(b))
#define UNPACK2(lo, hi, v) \
    asm("mov.b64 {%0, %1}, %2;" : "=f"(lo), "=f"(hi) : "l"(v))

// ============================================================================
// HMMA GEMM, W-persistent, bulk-copy loads: out = silu(A @ W^T) [+ skip]
// (R9 configuration — best measured: 64x64 tile, 2 CTAs/SM)
// ============================================================================
#define ASLAB (4096 * 128)          // bytes per activation slab (512KB)
#define A_ST  8192                   // A stage bytes (64 rows x 128B)
#define W_PB  65536                  // W persistent bytes (8 slabs x 8KB)
#define GEMM_SMEM (W_PB + 3 * A_ST)  // 90112 -> 2 CTAs/SM

__global__ void __launch_bounds__(256, 2) gemm_mma_kernel(
    const __nv_bfloat16* __restrict__ A2,
    const __nv_bfloat16* __restrict__ Wc,   // already offset to this gemm
    const float* __restrict__ skip,
    float* __restrict__ outf,
    __nv_bfloat16* __restrict__ out2)
{
    extern __shared__ char smem[];
    uint32_t sb = smem_u32(smem);            // [0,65536): W; then 3 A stages
    __shared__ __align__(8) uint64_t mbars[4];  // 0-2: A stages, 3: W

    int tid = threadIdx.x, wid = tid >> 5, lane = tid & 31;
    int m0 = blockIdx.y * 64, n0 = blockIdx.x * 64;
    int nb = blockIdx.x;
    int warp_m = (wid & 1) * 32, warp_n = (wid >> 1) * 16;

    uint32_t mb[3] = { smem_u32(&mbars[0]), smem_u32(&mbars[1]), smem_u32(&mbars[2]) };
    uint32_t wbar  = smem_u32(&mbars[3]);

    if (tid == 0) {
        MBAR_INIT(mb[0], 1);
        MBAR_INIT(mb[1], 1);
        MBAR_INIT(mb[2], 1);
        MBAR_INIT(wbar, 1);
    }
    __syncthreads();

    const char* gA = (const char*)A2 + (size_t)m0 * 128;   // + c*ASLAB per chunk
    const char* gW = (const char*)Wc + (size_t)nb * W_PB;

    if (tid == 0) {
        MBAR_EXPECT_TX(wbar, W_PB);
        CP_BULK(sb, gW, W_PB, wbar);
        MBAR_EXPECT_TX(mb[0], A_ST);
        CP_BULK(sb + W_PB, gA + 0 * (size_t)ASLAB, A_ST, mb[0]);
        MBAR_EXPECT_TX(mb[1], A_ST);
        CP_BULK(sb + W_PB + A_ST, gA + 1 * (size_t)ASLAB, A_ST, mb[1]);
    }

    float acc[2][2][4];
#pragma unroll
    for (int i = 0; i < 2; i++)
#pragma unroll
        for (int j = 0; j < 2; j++)
#pragma unroll
            for (int q = 0; q < 4; q++) acc[i][j][q] = 0.f;

    int arow0 = warp_m + (lane & 15);
    int brow  = warp_n + (lane & 15);
    int hi16  = (lane >> 4) * 16;

    MBAR_WAIT(wbar, 0);

#pragma unroll
    for (int ch = 0; ch < 8; ch++) {
        if (ch + 2 < 8 && tid == 0) {
            int ns = (ch + 2) % 3;
            MBAR_EXPECT_TX(mb[ns], A_ST);
            CP_BULK(sb + W_PB + ns * A_ST, gA + (size_t)(ch + 2) * ASLAB, A_ST, mb[ns]);
        }

        const int s = ch % 3;
        MBAR_WAIT(mb[s], (ch / 3) & 1);

        uint32_t aB = sb + W_PB + s * A_ST;
        const bool isHi = (ch < 4);
        const uint32_t whiB = sb + (uint32_t)((isHi ? ch : (ch - 4)) * 8192);
        const uint32_t wloB = sb + (uint32_t)((4 + ch) * 8192);

        uint32_t a[2][2][4], bh[2][4], bl[2][4];
        {
            uint32_t o0 = SWZ((uint32_t)(arow0 * 128 + hi16));
            uint32_t o1 = SWZ((uint32_t)((arow0 + 16) * 128 + hi16));
            LDMATRIX_X4(a[0][0][0], a[0][0][1], a[0][0][2], a[0][0][3], aB + o0);
            LDMATRIX_X4(a[0][1][0], a[0][1][1], a[0][1][2], a[0][1][3], aB + o1);
            uint32_t bo = SWZ((uint32_t)(brow * 128 + hi16));
            LDMATRIX_X4(bh[0][0], bh[0][1], bh[0][2], bh[0][3], whiB + bo);
            if (isHi) LDMATRIX_X4(bl[0][0], bl[0][1], bl[0][2], bl[0][3], wloB + bo);
        }

#pragma unroll
        for (int kh = 0; kh < 4; kh++) {
            const int cur = kh & 1, nxt = cur ^ 1;
            if (kh < 3) {
                uint32_t ko = (uint32_t)((kh + 1) * 32 + hi16);
                uint32_t o0 = SWZ((uint32_t)(arow0 * 128) + ko);
                uint32_t o1 = SWZ((uint32_t)((arow0 + 16) * 128) + ko);
                LDMATRIX_X4(a[nxt][0][0], a[nxt][0][1], a[nxt][0][2], a[nxt][0][3], aB + o0);
                LDMATRIX_X4(a[nxt][1][0], a[nxt][1][1], a[nxt][1][2], a[nxt][1][3], aB + o1);
                uint32_t bo = SWZ((uint32_t)(brow * 128) + ko);
                LDMATRIX_X4(bh[nxt][0], bh[nxt][1], bh[nxt][2], bh[nxt][3], whiB + bo);
                if (isHi) LDMATRIX_X4(bl[nxt][0], bl[nxt][1], bl[nxt][2], bl[nxt][3], wloB + bo);
            }
#pragma unroll
            for (int mt = 0; mt < 2; mt++)
#pragma unroll
                for (int j = 0; j < 2; j++)
                    MMA_BF16(acc[mt][j], a[cur][mt], bh[cur][j], bh[cur][j + 2]);
            if (isHi) {
#pragma unroll
                for (int mt = 0; mt < 2; mt++)
#pragma unroll
                    for (int j = 0; j < 2; j++)
                        MMA_BF16(acc[mt][j], a[cur][mt], bl[cur][j], bl[cur][j + 2]);
            }
        }

        __syncthreads();
    }

    // ---------------- epilogue ----------------
    char* o2 = (char*)out2;
    int r0 = lane >> 2, cp = (lane & 3) * 2;
#pragma unroll
    for (int mt = 0; mt < 2; mt++) {
#pragma unroll
        for (int j = 0; j < 2; j++) {
            int n = n0 + warp_n + j * 8 + cp;
#pragma unroll
            for (int half = 0; half < 2; half++) {
                int m = m0 + warp_m + mt * 16 + r0 + half * 8;
                float v0 = acc[mt][j][half * 2 + 0];
                float v1 = acc[mt][j][half * 2 + 1];
                v0 = silu(v0);
                v1 = silu(v1);
                if (skip) {
                    float2 sk = *reinterpret_cast<const float2*>(skip + (size_t)m * 256 + n);
                    v0 += sk.x; v1 += sk.y;
                }
                if (outf) {
                    float2 o; o.x = v0; o.y = v1;
                    *reinterpret_cast<float2*>(outf + (size_t)m * 256 + n) = o;
                }
                if (out2) {
                    __nv_bfloat16 h0 = __float2bfloat16(v0);
                    __nv_bfloat16 h1 = __float2bfloat16(v1);
                    __nv_bfloat162 hh; hh.x = h0; hh.y = h1;
                    __nv_bfloat162 ll;
                    ll.x = __float2bfloat16(v0 - __bfloat162float(h0));
                    ll.y = __float2bfloat16(v1 - __bfloat162float(h1));
                    uint32_t loc = SWZ((uint32_t)(m * 128 + (n & 63) * 2));
                    *reinterpret_cast<__nv_bfloat162*>(
                        o2 + (size_t)(n >> 6) * ASLAB + loc) = hh;
                    *reinterpret_cast<__nv_bfloat162*>(
                        o2 + (size_t)(4 + (n >> 6)) * ASLAB + loc) = ll;
                }
            }
        }
    }
}

// ---------------- hi/lo conversion of h (slabbed, swizzled) ----------------
__global__ void conv_h_kernel(const float* __restrict__ h) {
    int idx = blockIdx.x * 256 + threadIdx.x;
    int m = idx >> 8, e = idx & 255;
    float v = h[idx];
    __nv_bfloat16 hi = __float2bfloat16(v);
    __nv_bfloat16 lo = __float2bfloat16(v - __bfloat162float(hi));
    uint32_t loc = SWZ((uint32_t)(m * 128 + (e & 63) * 2));
    char* base = (char*)g_x2a;
    *reinterpret_cast<__nv_bfloat16*>(base + (size_t)(e >> 6) * ASLAB + loc) = hi;
    *reinterpret_cast<__nv_bfloat16*>(base + (size_t)(4 + (e >> 6)) * ASLAB + loc) = lo;
}

// ---------------- weight conversion (slabbed, swizzled) ----------------
__global__ void conv_w_kernel(const float* __restrict__ Wpre,
                              const float* __restrict__ W0,
                              const float* __restrict__ Wres) {
    int g = blockIdx.y;
    int i = blockIdx.x * 256 + threadIdx.x;  // 0..65535
    int n = i >> 8, k = i & 255;
    const float* src = (g < 2) ? (Wpre + (size_t)g * 65536)
                     : (g == 2) ? W0
                     : (Wres + (size_t)(g - 3) * 65536);
    float v = src[i];
    __nv_bfloat16 hi = __float2bfloat16(v);
    __nv_bfloat16 lo = __float2bfloat16(v - __bfloat162float(hi));
    uint32_t loc = SWZ((uint32_t)((n & 63) * 128 + (k & 63) * 2));
    char* base = (char*)g_wc + (size_t)g * 262144 + (size_t)(n >> 6) * W_PB;
    *reinterpret_cast<__nv_bfloat16*>(base + (size_t)(k >> 6) * 8192 + loc) = hi;
    *reinterpret_cast<__nv_bfloat16*>(base + (size_t)(4 + (k >> 6)) * 8192 + loc) = lo;
}

// ---------------- segment offsets from sorted batch_seg ----------------
__global__ void seg_offsets_kernel(const int* __restrict__ seg) {
    int n = blockIdx.x * blockDim.x + threadIdx.x;
    if (n >= NN) return;
    int s = seg[n];
    if (n == 0) {
        for (int b = 0; b <= s; b++) g_off[b] = 0;
    } else {
        int p = seg[n - 1];
        for (int b = p + 1; b <= s; b++) g_off[b] = n;
    }
    if (n == NN - 1) {
        for (int b = s + 1; b <= BB; b++) g_off[b] = NN;
    }
}

// ---------------- dot products + cos/sin ----------------
__global__ void dot_kernel(const float* __restrict__ x,
                           const float* __restrict__ kvec,
                           const int* __restrict__ seg,
                           float* __restrict__ dot_out) {
    int n = blockIdx.x;
    int kk = threadIdx.x;  // 128
    int b = seg[n];
    float x0 = x[n * 3 + 0], x1 = x[n * 3 + 1], x2 = x[n * 3 + 2];
    const float* kr = kvec + ((size_t)b * KK + kk) * 3;
    float d = kr[0] * x0 + kr[1] * x1 + kr[2] * x2;
    dot_out[n * KK + kk] = d;
    float cv, sv;
    sincosf(d, &sv, &cv);
    g_c[n * KK + kk] = cv;
    g_s[n * KK + kk] = sv;
}

// ---------------- low-rank k-filter ----------------
__global__ void kf_kernel(const float* __restrict__ Wup,
                          const float* __restrict__ Wdn) {
    int e = threadIdx.x;
    int k = blockIdx.x;
    float a = 0.f;
#pragma unroll
    for (int d = 0; d < DD; d++) a += Wup[e * DD + d] * Wdn[d * KK + k];
    g_kf[k * EE + e] = a;
}

// ---------------- structure factors (kfilter folded in, f32x2 FMA) ----------
__global__ void __launch_bounds__(256, 4) sf_kernel() {
    int b  = blockIdx.z;
    int k0 = blockIdx.y * 32;
    int e0 = blockIdx.x * 32;
    int t = threadIdx.x;
    int e4 = t & 7;
    int ky = t >> 3;
    __shared__ float csh[32][32], ssh[32][32];
    __shared__ __align__(16) float hsh[32][32];
    int st = g_off[b], en = g_off[b + 1];
    uint64_t aR01 = 0, aR23 = 0, aI01 = 0, aI23 = 0;  // bit 0 == {0.f,0.f}
    uint32_t hbase = smem_u32(&hsh[0][0]) + e4 * 16;
    for (int n0 = st; n0 < en; n0 += 32) {
#pragma unroll
        for (int l = 0; l < 4; l++) {
            int idx = t + 256 * l;
            int r = idx >> 5, c = idx & 31;
            int n = n0 + r;
            bool v = (n < en);
            csh[r][c] = v ? g_c[n * KK + k0 + c] : 0.f;
            ssh[r][c] = v ? g_s[n * KK + k0 + c] : 0.f;
            hsh[r][c] = v ? g_hres[(size_t)n * EE + e0 + c] : 0.f;
        }
        __syncthreads();
#pragma unroll
        for (int nn = 0; nn < 32; nn++) {
            uint64_t h01, h23, cv2, sv2;
            asm volatile("ld.shared.v2.u64 {%0, %1}, [%2];"
                         : "=l"(h01), "=l"(h23) : "r"(hbase + nn * 128));
            float cv = csh[nn][ky], sv = ssh[nn][ky];
            PACK2(cv2, cv);
            PACK2(sv2, sv);
            FMA2(aR01, cv2, h01);
            FMA2(aR23, cv2, h23);
            FMA2(aI01, sv2, h01);
            FMA2(aI23, sv2, h23);
        }
        __syncthreads();
    }
    float aR[4], aI[4];
    UNPACK2(aR[0], aR[1], aR01);
    UNPACK2(aR[2], aR[3], aR23);
    UNPACK2(aI[0], aI[1], aI01);
    UNPACK2(aI[2], aI[3], aI23);
    float4 f = *reinterpret_cast<float4*>(&g_kf[(k0 + ky) * EE + e0 + e4 * 4]);
    size_t idx = ((size_t)b * KK + k0 + ky) * EE + e0 + e4 * 4;
    float4 oR, oI;
    oR.x = aR[0] * f.x; oR.y = aR[1] * f.y; oR.z = aR[2] * f.z; oR.w = aR[3] * f.w;
    oI.x = aI[0] * f.x; oI.y = aI[1] * f.y; oI.z = aI[2] * f.z; oI.w = aI[3] * f.w;
    *reinterpret_cast<float4*>(&g_sfr[idx]) = oR;
    *reinterpret_cast<float4*>(&g_sfi[idx]) = oI;
}

// ---------------- back-projection (f32x2 FMA); writes hi/lo bf16 slabs ------
__global__ void __launch_bounds__(256, 4) hupd_kernel(const int* __restrict__ seg) {
    int n0 = blockIdx.y * 32;
    int e0 = blockIdx.x * 32;
    int t = threadIdx.x;
    int e4 = t & 7;
    int ny = t >> 3;
    int n = n0 + ny;
    int b = seg[n];
    __shared__ float csh[32][32], ssh[32][32];
    uint64_t acc01 = 0, acc23 = 0;
    for (int k0c = 0; k0c < KK; k0c += 32) {
#pragma unroll
        for (int l = 0; l < 4; l++) {
            int idx = t + 256 * l;
            int r = idx >> 5, c = idx & 31;
            csh[r][c] = g_c[(n0 + r) * KK + k0c + c];
            ssh[r][c] = g_s[(n0 + r) * KK + k0c + c];
        }
        __syncthreads();
        const ulonglong2* baseR = reinterpret_cast<const ulonglong2*>(
            g_sfr + ((size_t)b * KK + k0c) * EE + e0 + e4 * 4);
        const ulonglong2* baseI = reinterpret_cast<const ulonglong2*>(
            g_sfi + ((size_t)b * KK + k0c) * EE + e0 + e4 * 4);
#pragma unroll
        for (int kk = 0; kk < 32; kk++) {
            float cv = csh[ny][kk];
            float sv = ssh[ny][kk];
            uint64_t cv2, sv2;
            PACK2(cv2, cv);
            PACK2(sv2, sv);
            ulonglong2 pr = baseR[(size_t)kk * (EE / 4)];
            ulonglong2 pi = baseI[(size_t)kk * (EE / 4)];
            FMA2(acc01, cv2, pr.x);
            FMA2(acc23, cv2, pr.y);
            FMA2(acc01, sv2, pi.x);
            FMA2(acc23, sv2, pi.y);
        }
        __syncthreads();
    }
    float acc[4];
    UNPACK2(acc[0], acc[1], acc01);
    UNPACK2(acc[2], acc[3], acc23);
    __nv_bfloat16 hi[4], lo[4];
#pragma unroll
    for (int q = 0; q < 4; q++) {
        float v = 0.01f * acc[q];
        hi[q] = __float2bfloat16(v);
        lo[q] = __float2bfloat16(v - __bfloat162float(hi[q]));
    }
    int e = e0 + e4 * 4;
    uint32_t loc = SWZ((uint32_t)(n * 128 + (e & 63) * 2));
    char* base = (char*)g_x2a;
    *reinterpret_cast<uint2*>(base + (size_t)(e >> 6) * ASLAB + loc) =
        *reinterpret_cast<uint2*>(hi);
    *reinterpret_cast<uint2*>(base + (size_t)(4 + (e >> 6)) * ASLAB + loc) =
        *reinterpret_cast<uint2*>(lo);
}

// ---------------- launch ----------------
extern "C" void kernel_launch(void* const* d_in, const int* in_sizes, int n_in,
                              void* d_out, int out_size) {
    const float *h = nullptr, *x = nullptr, *kv = nullptr;
    const float *Wpre = nullptr, *Wdn = nullptr, *Wup = nullptr;
    const float *W0 = nullptr, *Wres = nullptr;
    const int* seg = nullptr;

    for (int i = 0; i < n_in; i++) {
        switch (in_sizes[i]) {
            case NN * EE:           h    = (const float*)d_in[i]; break;
            case NN * 3:            x    = (const float*)d_in[i]; break;
            case BB * KK * 3:       kv   = (const float*)d_in[i]; break;
            case NN:                seg  = (const int*)d_in[i];   break;
            case 2 * EE * EE:       Wpre = (const float*)d_in[i]; break;
            case DD * KK:           Wdn  = (const float*)d_in[i]; break;
            case EE * DD:           Wup  = (const float*)d_in[i]; break;
            case EE * EE:           W0   = (const float*)d_in[i]; break;
            case 3 * 2 * EE * EE:   Wres = (const float*)d_in[i]; break;
            default: break;
        }
    }

    float* out = (float*)d_out;
    float* out_hu  = out;            // (NN, EE)
    float* out_dot = out + NN * EE;  // (NN, KK)

    float *t0, *hres;
    __nv_bfloat16 *x2a, *x2b, *wc;
    cudaGetSymbolAddress((void**)&t0,   g_t0);
    cudaGetSymbolAddress((void**)&hres, g_hres);
    cudaGetSymbolAddress((void**)&x2a,  g_x2a);
    cudaGetSymbolAddress((void**)&x2b,  g_x2b);
    cudaGetSymbolAddress((void**)&wc,   g_wc);

    cudaFuncSetAttribute(gemm_mma_kernel,
                         cudaFuncAttributeMaxDynamicSharedMemorySize, GEMM_SMEM);
    dim3 ggrid(EE / 64, NN / 64);  // (4, 64) = 256 CTAs -> 2/SM

    // conversions
    conv_w_kernel<<<dim3(256, 9), 256>>>(Wpre, W0, Wres);
    conv_h_kernel<<<NN * EE / 256, 256>>>(h);

    // pre-residual: x2b = silu(h@W0'), hres = h + silu(x2b@W1')
    gemm_mma_kernel<<<ggrid, 256, GEMM_SMEM>>>(x2a, wc + 0 * 131072, nullptr, nullptr, x2b);
    gemm_mma_kernel<<<ggrid, 256, GEMM_SMEM>>>(x2b, wc + 1 * 131072, h, hres, nullptr);

    // Ewald geometry path
    seg_offsets_kernel<<<(NN + 255) / 256, 256>>>(seg);
    dot_kernel<<<NN, KK>>>(x, kv, seg, out_dot);
    kf_kernel<<<KK, EE>>>(Wup, Wdn);
    sf_kernel<<<dim3(EE / 32, KK / 32, BB), 256>>>();
    hupd_kernel<<<dim3(EE / 32, NN / 32), 256>>>(seg);  // -> g_x2a (slabbed hi/lo)

    // update MLP: t0 = silu(hu @ W0^T)
    gemm_mma_kernel<<<ggrid, 256, GEMM_SMEM>>>(x2a, wc + 2 * 131072, nullptr, t0, x2b);

    // 3 residual blocks
    for (int i = 0; i < 3; i++) {
        const __nv_bfloat16* wa = wc + (size_t)(3 + 2 * i) * 131072;
        const __nv_bfloat16* wb = wc + (size_t)(4 + 2 * i) * 131072;
        gemm_mma_kernel<<<ggrid, 256, GEMM_SMEM>>>(x2b, wa, nullptr, nullptr, x2a);
        float* dstf = (i == 2) ? out_hu : t0;
        __nv_bfloat16* dst2 = (i == 2) ? nullptr : x2b;
        gemm_mma_kernel<<<ggrid, 256, GEMM_SMEM>>>(x2a, wb, t0, dstf, dst2);
    }
}